// round 9
// baseline (speedup 1.0000x reference)
#include <cuda_runtime.h>
#include <cuda_bf16.h>
#include <math.h>
#include <stdint.h>

#define NH 12
#define NB 16
#define NS 512
#define ND 768
#define NF 3072
#define NL 4
#define NDH 64
#define MROWS (NB*NS)      // 8192
#define NBH (NB*NH)        // 192

typedef __nv_bfloat16 bf16;

#if defined(__CUDA_ARCH_FEAT_SM103_ALL)
#define HAS_TC 1
#else
#define HAS_TC 0
#endif

// ---------------- scratch ----------------
__device__ float g_xf[MROWS*ND];
__device__ float g_tmp[MROWS*ND];
__device__ float g_attnf[MROWS*ND];
__device__ float g_cninv[NBH*NS];

__device__ bf16 g_xh[MROWS*ND],   g_xl[MROWS*ND];
__device__ bf16 g_prjh[(size_t)MROWS*4*ND], g_prjl[(size_t)MROWS*4*ND]; // q|k|c|v
__device__ bf16 g_ctxh[MROWS*ND], g_ctxl[MROWS*ND];
__device__ bf16 g_ath[MROWS*ND],  g_atl[MROWS*ND];
__device__ bf16 g_hh[(size_t)MROWS*NF], g_hl[(size_t)MROWS*NF];
__device__ bf16 g_vth[NBH*NDH*NS], g_vtl[NBH*NDH*NS];

#define WDD (768*768)
#define WDF (768*3072)
#define CATW (4*WDD)
__device__ bf16 g_wcath[NL*CATW], g_wcatl[NL*CATW];
__device__ bf16 g_woh[NL*WDD], g_wol[NL*WDD];
__device__ bf16 g_wih[NL*WDF], g_wil[NL*WDF];
__device__ bf16 g_wo2h[NL*WDF], g_wo2l[NL*WDF];
__device__ float g_bcat[NL*4*ND];

// ---------------- helpers ----------------
__device__ __forceinline__ void split2(float v, bf16& h, bf16& l) {
    h = __float2bfloat16(v);
    l = __float2bfloat16(v - __bfloat162float(h));
}

__device__ __forceinline__ void cpa16(uint32_t dst, const void* src, int sz) {
    asm volatile("cp.async.cg.shared.global [%0], [%1], 16, %2;" :: "r"(dst), "l"(src), "r"(sz));
}

#define FENCE_PROXY_ASYNC() \
    asm volatile("fence.proxy.async.shared::cta;" ::: "memory")

#define STS128X(r0,r1,r2,r3,addr) \
    asm volatile("st.shared.v4.b32 [%0], {%1,%2,%3,%4};" \
        :: "r"(addr), "r"(r0), "r"(r1), "r"(r2), "r"(r3) : "memory")

#if HAS_TC
__device__ __forceinline__ uint32_t elect_one_pred() {
    uint32_t pred;
    asm volatile(
        "{\n\t.reg .pred p;\n\t"
        "elect.sync _|p, 0xFFFFFFFF;\n\t"
        "selp.b32 %0, 1, 0, p;\n\t}"
        : "=r"(pred));
    return pred;
}

static constexpr uint64_t SMEM_DESC_BASE_SW128 =
    (uint64_t(2) << 61) | (uint64_t(1) << 46) | (uint64_t(64) << 32) | (uint64_t(1) << 16);
#define MAKE_SMEM_DESC(base_addr) \
    (SMEM_DESC_BASE_SW128 | ((uint64_t)((base_addr) >> 4) & 0x3FFF))

#define TCGEN05_ALLOC(smem_result_addr, nCols) \
    asm volatile("tcgen05.alloc.cta_group::1.sync.aligned.shared::cta.b32 [%0], %1;" \
        :: "r"((uint32_t)(smem_result_addr)), "r"((uint32_t)(nCols)) : "memory")
#define TCGEN05_DEALLOC(tmem_addr, nCols) \
    asm volatile("tcgen05.dealloc.cta_group::1.sync.aligned.b32 %0, %1;" \
        :: "r"(tmem_addr), "r"((uint32_t)(nCols)))
#define TCGEN05_RELINQ() \
    asm volatile("tcgen05.relinquish_alloc_permit.cta_group::1.sync.aligned;")
#define TCGEN05_COMMIT(mbar) \
    asm volatile("tcgen05.commit.cta_group::1.mbarrier::arrive::one.shared::cluster.b64 [%0];" \
        :: "r"((uint32_t)(mbar)) : "memory")
#define TCGEN05_WAIT_LD() \
    asm volatile("tcgen05.wait::ld.sync.aligned;" ::: "memory")
#define TCGEN05_FENCE_AFTER() \
    asm volatile("tcgen05.fence::after_thread_sync;" ::: "memory")
#define TCGEN05_FENCE_BEFORE() \
    asm volatile("tcgen05.fence::before_thread_sync;" ::: "memory")

#define MBARRIER_INIT(mbar, count) \
    asm volatile("mbarrier.init.shared.b64 [%0], %1;" \
        :: "r"((uint32_t)(mbar)), "r"((uint32_t)(count)) : "memory")
#define MBARRIER_INVAL(mbar) \
    asm volatile("mbarrier.inval.shared.b64 [%0];" :: "r"((uint32_t)(mbar)) : "memory")
#define MBARRIER_WAIT_PARITY(mbar_addr, phase_parity) do { \
    uint32_t _mbar = (uint32_t)(mbar_addr); \
    uint32_t _parity = (uint32_t)(phase_parity); \
    uint32_t _done; \
    asm volatile( \
        "{\n\t.reg .pred p;\n\t" \
        "mbarrier.try_wait.parity.acquire.cta.shared::cta.b64 p, [%1], %2;\n\t" \
        "selp.b32 %0, 1, 0, p;\n\t}" \
        : "=r"(_done) : "r"(_mbar), "r"(_parity) : "memory"); \
    if (!_done) { \
        asm volatile( \
            "{\n\t.reg .pred P1;\n\t" \
            "WAIT_LOOP_%=:\n\t" \
            "mbarrier.try_wait.parity.acquire.cta.shared::cta.b64 P1, [%0], %1, 0x989680;\n\t" \
            "@P1 bra.uni WAIT_DONE_%=;\n\t" \
            "bra.uni WAIT_LOOP_%=;\n\t" \
            "WAIT_DONE_%=:\n\t}" \
            :: "r"(_mbar), "r"(_parity) : "memory"); \
    } \
} while(0)

#define TCGEN05_LD_32X32B_X32(r, tmem_addr) \
    asm volatile( \
        "tcgen05.ld.sync.aligned.32x32b.x32.b32 " \
        "{%0, %1, %2, %3, %4, %5, %6, %7, " \
        " %8, %9, %10, %11, %12, %13, %14, %15, " \
        " %16, %17, %18, %19, %20, %21, %22, %23, " \
        " %24, %25, %26, %27, %28, %29, %30, %31}, [%32];" \
        : "=r"((r)[0]),  "=r"((r)[1]),  "=r"((r)[2]),  "=r"((r)[3]), \
          "=r"((r)[4]),  "=r"((r)[5]),  "=r"((r)[6]),  "=r"((r)[7]), \
          "=r"((r)[8]),  "=r"((r)[9]),  "=r"((r)[10]), "=r"((r)[11]), \
          "=r"((r)[12]), "=r"((r)[13]), "=r"((r)[14]), "=r"((r)[15]), \
          "=r"((r)[16]), "=r"((r)[17]), "=r"((r)[18]), "=r"((r)[19]), \
          "=r"((r)[20]), "=r"((r)[21]), "=r"((r)[22]), "=r"((r)[23]), \
          "=r"((r)[24]), "=r"((r)[25]), "=r"((r)[26]), "=r"((r)[27]), \
          "=r"((r)[28]), "=r"((r)[29]), "=r"((r)[30]), "=r"((r)[31]) \
        : "r"(tmem_addr))

__device__ __forceinline__ void mma_f16_ss(uint32_t d, uint64_t ad, uint64_t bd,
                                           uint32_t idesc, uint32_t en) {
    asm volatile(
        "{\n\t.reg .pred p;\n\t"
        "setp.ne.u32 p, %5, 0;\n\t"
        "tcgen05.mma.cta_group::1.kind::f16 [%0], %1, %2, %3, {%4, %4, %4, %4}, p;\n\t}"
        :: "r"(d), "l"(ad), "l"(bd), "r"(idesc), "r"(0u), "r"(en) : "memory");
}
#endif

// ---------------- bf16x3 NT GEMM (R5/R8 proven engine, 128 x TN) ----------------
// EPI: 1 f32+bias, 2 pair+bias, 4 pair+bias+gelu
template<int EPI, int TN>
__global__ void __launch_bounds__(256) gemm_tc(
    const bf16* __restrict__ Ah_, const bf16* __restrict__ Al_,
    int lda, long long sAb, long long sAh,
    const bf16* __restrict__ Bh_, const bf16* __restrict__ Bl_,
    int ldb, long long sBb, long long sBh,
    float* __restrict__ Cf, bf16* __restrict__ Coh, bf16* __restrict__ Col,
    int ldc, long long sCb, long long sCh,
    const float* __restrict__ bias,
    int N, int K, int Hdiv, uint32_t idesc)
{
    constexpr int STAGE = (128 + TN) * 256;
    constexpr int AHOF = 0, ALOF = 16384, BHOF = 32768, BLOF = 32768 + TN * 128;
    extern __shared__ __align__(1024) char dsm[];
    const int tid = threadIdx.x, lane = tid & 31, wid = tid >> 5;
    const int zb = blockIdx.z / Hdiv, zh = blockIdx.z % Hdiv;
    const int m0 = blockIdx.y * 128, n0 = blockIdx.x * TN;
    const int nB = min(TN, N - n0);

    const bf16* Agh = Ah_ + zb*sAb + zh*sAh + (long long)m0 * lda;
    const bf16* Agl = Al_ + zb*sAb + zh*sAh + (long long)m0 * lda;
    const bf16* Bgh = Bh_ + zb*sBb + zh*sBh + (long long)n0 * ldb;
    const bf16* Bgl = Bl_ + zb*sBb + zh*sBh + (long long)n0 * ldb;

    float* Cfp = Cf  ? Cf  + zb*sCb + zh*sCh : nullptr;
    bf16*  Chp = Coh ? Coh + zb*sCb + zh*sCh : nullptr;
    bf16*  Clp = Col ? Col + zb*sCb + zh*sCh : nullptr;

#if HAS_TC
    const int nst = (K > 64) ? 2 : 1;
    uint32_t sb  = (uint32_t)__cvta_generic_to_shared(dsm);
    uint32_t ctl = sb + (uint32_t)(nst * STAGE);
    uint32_t mb0 = ctl + 8, mb1 = ctl + 16;

    if (tid == 0) { MBARRIER_INIT(mb0, 1); MBARRIER_INIT(mb1, 1); }
    if (wid == 4) { TCGEN05_ALLOC(ctl, TN); TCGEN05_RELINQ(); }
    __syncthreads();
    uint32_t tmem;
    asm volatile("ld.shared.b32 %0, [%1];" : "=r"(tmem) : "r"(ctl));

    const int KT = K >> 6;
    int ph0 = 0, ph1 = 0;

    auto issue = [&](int buf, int k0) {
        const uint32_t sbase = sb + (uint32_t)(buf * STAGE);
        constexpr int ITER = (128 + TN) * 8 / 256;
        #pragma unroll
        for (int i = 0; i < ITER; i++) {
            int id = tid + (i << 8);
            int row = id >> 3, cc = id & 7;
            if (row < 128) {
                uint32_t off = (uint32_t)((row << 7) + (cc << 4));
                uint32_t sw = off ^ ((off >> 3) & 0x70);
                long long ga = (long long)row * lda + k0 + (cc << 3);
                cpa16(sbase + AHOF + sw, Agh + ga, 16);
                cpa16(sbase + ALOF + sw, Agl + ga, 16);
            } else {
                int rb = row - 128;
                uint32_t off = (uint32_t)((rb << 7) + (cc << 4));
                uint32_t sw = off ^ ((off >> 3) & 0x70);
                int sz = 16, br = rb;
                if (rb >= nB) { sz = 0; br = 0; }
                long long gb = (long long)br * ldb + k0 + (cc << 3);
                cpa16(sbase + BHOF + sw, Bgh + gb, sz);
                cpa16(sbase + BLOF + sw, Bgl + gb, sz);
            }
        }
        asm volatile("cp.async.commit_group;");
    };

    issue(0, 0);
    for (int kt = 0; kt < KT; kt++) {
        const int buf = (nst == 2) ? (kt & 1) : 0;
        if (kt + 1 < KT) {
            if (kt >= 1) {
                if ((buf ^ 1) == 0) { MBARRIER_WAIT_PARITY(mb0, ph0); ph0 ^= 1; }
                else                { MBARRIER_WAIT_PARITY(mb1, ph1); ph1 ^= 1; }
            }
            issue(buf ^ 1, (kt + 1) << 6);
            asm volatile("cp.async.wait_group 1;");
        } else {
            asm volatile("cp.async.wait_group 0;");
        }
        FENCE_PROXY_ASYNC();
        __syncthreads();

        const uint32_t sbase = sb + (uint32_t)(buf * STAGE);
        if (wid == 4) {
            if (elect_one_pred()) {
                uint64_t dah = MAKE_SMEM_DESC(sbase + AHOF);
                uint64_t dal = MAKE_SMEM_DESC(sbase + ALOF);
                uint64_t dbh = MAKE_SMEM_DESC(sbase + BHOF);
                uint64_t dbl = MAKE_SMEM_DESC(sbase + BLOF);
                #pragma unroll
                for (int s = 0; s < 4; s++) {
                    uint32_t en0 = (kt == 0 && s == 0) ? 0u : 1u;
                    mma_f16_ss(tmem, dah + s*2, dbh + s*2, idesc, en0);
                    mma_f16_ss(tmem, dah + s*2, dbl + s*2, idesc, 1u);
                    mma_f16_ss(tmem, dal + s*2, dbh + s*2, idesc, 1u);
                }
                TCGEN05_COMMIT(buf ? mb1 : mb0);
            }
        }
        __syncthreads();
    }

    const int lastbuf = (nst == 2) ? ((KT - 1) & 1) : 0;
    if (lastbuf == 0) { MBARRIER_WAIT_PARITY(mb0, ph0); }
    else              { MBARRIER_WAIT_PARITY(mb1, ph1); }
    TCGEN05_FENCE_AFTER();

    // epilogue: TMEM -> SMEM pivot -> coalesced stores (R5 proven)
    float* stg = (float*)dsm;
    for (int cb = 0; cb < nB; cb += 32) {
        if (wid < 4) {
            uint32_t d[32];
            TCGEN05_LD_32X32B_X32(d, tmem + cb);
            TCGEN05_WAIT_LD();
            int row = (wid << 5) + lane;
            #pragma unroll
            for (int j = 0; j < 32; j++) stg[row * 33 + j] = __uint_as_float(d[j]);
        }
        __syncthreads();
        #pragma unroll
        for (int it = 0; it < 4; it++) {
            int row = (it << 5) + (tid >> 3);
            int cc = (tid & 7) << 2;
            int gc = n0 + cb + cc;
            long long o = (long long)(m0 + row) * ldc + gc;
            float v[4];
            #pragma unroll
            for (int j = 0; j < 4; j++) {
                v[j] = stg[row * 33 + cc + j];
                if (EPI == 1 || EPI == 2 || EPI == 4) v[j] += bias[gc + j];
                if (EPI == 4) v[j] = 0.5f * v[j] * (1.0f + erff(v[j] * 0.70710678118654752f));
            }
            if (EPI <= 1) {
                *(float4*)(Cfp + o) = make_float4(v[0], v[1], v[2], v[3]);
            } else {
                bf16 h[4], l[4];
                #pragma unroll
                for (int j = 0; j < 4; j++) split2(v[j], h[j], l[j]);
                ((__nv_bfloat162*)(Chp + o))[0] = __nv_bfloat162(h[0], h[1]);
                ((__nv_bfloat162*)(Chp + o))[1] = __nv_bfloat162(h[2], h[3]);
                ((__nv_bfloat162*)(Clp + o))[0] = __nv_bfloat162(l[0], l[1]);
                ((__nv_bfloat162*)(Clp + o))[1] = __nv_bfloat162(l[2], l[3]);
            }
        }
        __syncthreads();
    }

    TCGEN05_FENCE_BEFORE();
    __syncthreads();
    if (tid == 0) { MBARRIER_INVAL(mb0); MBARRIER_INVAL(mb1); }
    if (wid == 4) TCGEN05_DEALLOC(tmem, TN);
#else
    for (int o = tid; o < 128 * TN; o += 256) {
        int m = o / TN, n = o % TN;
        if (n >= nB) continue;
        float s = 0.f;
        const bf16* arh = Agh + (long long)m * lda;
        const bf16* arl = Agl + (long long)m * lda;
        const bf16* brh = Bgh + (long long)n * ldb;
        const bf16* brl = Bgl + (long long)n * ldb;
        for (int k = 0; k < K; k++)
            s += (__bfloat162float(arh[k]) + __bfloat162float(arl[k])) *
                 (__bfloat162float(brh[k]) + __bfloat162float(brl[k]));
        int gc = n0 + n;
        if (EPI == 1 || EPI == 2 || EPI == 4) s += bias[gc];
        if (EPI == 4) s = 0.5f * s * (1.0f + erff(s * 0.70710678118654752f));
        long long off = (long long)(m0 + m) * ldc + gc;
        if (EPI <= 1) Cfp[off] = s;
        else split2(s, Chp[off], Clp[off]);
    }
#endif
}

// ================== fused attention: scores + dual softmax + P·Vt ==================
// per CTA: one (bh, 128-row m-tile). TMEM(512) holds one full score matrix.
#define FA_QA_H 0u
#define FA_QA_L 16384u
#define FA_CA_H 32768u
#define FA_CA_L 49152u
#define FA_BK0_H 65536u
#define FA_BK0_L 98304u
#define FA_BK1_H 131072u
#define FA_BK1_L 163840u
#define FA_P_H0 65536u
#define FA_P_L0 81920u
#define FA_P_H1 98304u
#define FA_P_L1 114688u
#define FA_VT_H0 131072u
#define FA_VT_L0 139264u
#define FA_VT_H1 147456u
#define FA_VT_L1 155648u
#define FA_STASH 0u
#define FA_CN 196608u
#define FA_RMAX 198656u
#define FA_RSUM 199680u
#define FA_CTL 200704u
#define FA_MBAR 200712u
#define FA_SMEM 200768

#define ID_S (0x8000490u | (32u << 17))
#define ID_C (0x8000490u | (8u << 17))

__global__ void __launch_bounds__(256) fused_attn(
    const bf16* __restrict__ PRH, const bf16* __restrict__ PRL,
    const bf16* __restrict__ VGH, const bf16* __restrict__ VGL,
    const float* __restrict__ CNG,
    bf16* __restrict__ OH, bf16* __restrict__ OL)
{
    extern __shared__ __align__(1024) char dsm[];
    const int tid = threadIdx.x, lane = tid & 31, wid = tid >> 5;
    const int bh = blockIdx.y, m0 = blockIdx.x * 128;
    const int zb = bh / NH, zh = bh % NH;

#if HAS_TC
    uint32_t sb = (uint32_t)__cvta_generic_to_shared(dsm);
    if (tid == 0) MBARRIER_INIT(sb + FA_MBAR, 1);
    if (wid == 4) { TCGEN05_ALLOC(sb + FA_CTL, 512); TCGEN05_RELINQ(); }
    __syncthreads();
    uint32_t tmem;
    asm volatile("ld.shared.b32 %0, [%1];" : "=r"(tmem) : "r"(sb + FA_CTL));
    int ph = 0;

    float* cns  = (float*)(dsm + FA_CN);
    float* rmax = (float*)(dsm + FA_RMAX);
    float* rsum = (float*)(dsm + FA_RSUM);
    float* stash = (float*)(dsm + FA_STASH);

    const long long rowbase = (long long)(zb * NS + m0) * 3072;
    const long long keybase = (long long)(zb * NS) * 3072;

    for (int i = tid; i < 512; i += 256) cns[i] = CNG[bh * 512 + i];

    auto tileload = [&](uint32_t dH, uint32_t dL, long long gbase, int nrows) {
        int tot = nrows * 8;
        for (int i = tid; i < tot; i += 256) {
            int r = i >> 3, cc = i & 7;
            uint32_t off = (uint32_t)((r << 7) + (cc << 4));
            uint32_t sw = off ^ ((off >> 3) & 0x70);
            long long g = gbase + (long long)r * 3072 + (cc << 3);
            cpa16(sb + dH + sw, PRH + g, 16);
            cpa16(sb + dL + sw, PRL + g, 16);
        }
    };

    tileload(FA_QA_H, FA_QA_L, rowbase + 0    + zh * 64, 128);
    tileload(FA_CA_H, FA_CA_L, rowbase + 1536 + zh * 64, 128);
    tileload(FA_BK0_H, FA_BK0_L, keybase + 768 + zh * 64, 256);
    tileload(FA_BK1_H, FA_BK1_L, keybase + 768 + zh * 64 + 256LL * 3072, 256);
    asm volatile("cp.async.commit_group;");
    asm volatile("cp.async.wait_group 0;");
    FENCE_PROXY_ASYNC();
    __syncthreads();

    const int sp = wid & 3, half = wid >> 2;
    const int rowl = sp * 32 + lane;

    auto do_branch = [&](int br) {
        // ---- S MMAs: full 128x512 scores into TMEM ----
        if (wid == 0) {
            if (elect_one_pred()) {
                uint64_t dA  = MAKE_SMEM_DESC(sb + (br ? FA_CA_H : FA_QA_H));
                uint64_t dAl = MAKE_SMEM_DESC(sb + (br ? FA_CA_L : FA_QA_L));
                #pragma unroll
                for (int h = 0; h < 2; h++) {
                    uint64_t dB  = MAKE_SMEM_DESC(sb + (h ? FA_BK1_H : FA_BK0_H));
                    uint64_t dBl = MAKE_SMEM_DESC(sb + (h ? FA_BK1_L : FA_BK0_L));
                    #pragma unroll
                    for (int s = 0; s < 4; s++) {
                        mma_f16_ss(tmem + h * 256, dA + s*2, dB + s*2, ID_S, (s == 0) ? 0u : 1u);
                        mma_f16_ss(tmem + h * 256, dA + s*2, dBl + s*2, ID_S, 1u);
                        mma_f16_ss(tmem + h * 256, dAl + s*2, dB + s*2, ID_S, 1u);
                    }
                }
                TCGEN05_COMMIT(sb + FA_MBAR);
            }
        }
        MBARRIER_WAIT_PARITY(sb + FA_MBAR, ph); ph ^= 1;
        TCGEN05_FENCE_AFTER();

        const float cl = cns[m0 + rowl];
        auto xf = [&](float raw, int gcol) -> float {
            if (br) return 1.0f - raw * cl * cns[gcol] + ((gcol == m0 + rowl) ? 1.0f : 0.0f);
            else    return raw * 0.125f;
        };

        // ---- pass 1: row max (per-lane; halves combined via smem) ----
        float lmax = -1e30f;
        for (int c8 = 0; c8 < 8; c8++) {
            uint32_t d[32];
            TCGEN05_LD_32X32B_X32(d, tmem + half * 256 + c8 * 32);
            TCGEN05_WAIT_LD();
            #pragma unroll
            for (int j = 0; j < 32; j++)
                lmax = fmaxf(lmax, xf(__uint_as_float(d[j]), half * 256 + c8 * 32 + j));
        }
        rmax[rowl * 2 + half] = lmax;
        __syncthreads();
        float gmax = fmaxf(rmax[rowl * 2], rmax[rowl * 2 + 1]);

        // ---- pass 1b: exp-sum ----
        float lsum = 0.f;
        for (int c8 = 0; c8 < 8; c8++) {
            uint32_t d[32];
            TCGEN05_LD_32X32B_X32(d, tmem + half * 256 + c8 * 32);
            TCGEN05_WAIT_LD();
            #pragma unroll
            for (int j = 0; j < 32; j++)
                lsum += __expf(xf(__uint_as_float(d[j]), half * 256 + c8 * 32 + j) - gmax);
        }
        rsum[rowl * 2 + half] = lsum;
        __syncthreads();
        const float inv = 0.5f / (rsum[rowl * 2] + rsum[rowl * 2 + 1]);   // 0.5 = blend weight

        // ---- pass 2: per 128-key chunk, P -> SMEM, ctx MMA into TMEM[0:64) ----
        for (int j = 0; j < 4; j++) {
            // VT chunk loads (both k-subtiles)
            for (int i = tid; i < 64 * 8; i += 256) {
                int d_ = i >> 3, cc = i & 7;
                uint32_t off = (uint32_t)((d_ << 7) + (cc << 4));
                uint32_t sw = off ^ ((off >> 3) & 0x70);
                long long g = (long long)bh * (64LL * 512) + (long long)d_ * 512 + j * 128 + (cc << 3);
                cpa16(sb + FA_VT_H0 + sw, VGH + g, 16);
                cpa16(sb + FA_VT_L0 + sw, VGL + g, 16);
                cpa16(sb + FA_VT_H1 + sw, VGH + g + 64, 16);
                cpa16(sb + FA_VT_L1 + sw, VGL + g + 64, 16);
            }
            asm volatile("cp.async.commit_group;");

            if (half == (j >> 1)) {
                for (int cc = 0; cc < 4; cc++) {
                    uint32_t d[32];
                    TCGEN05_LD_32X32B_X32(d, tmem + j * 128 + cc * 32);
                    TCGEN05_WAIT_LD();
                    float p[32];
                    #pragma unroll
                    for (int e = 0; e < 32; e++)
                        p[e] = __expf(xf(__uint_as_float(d[e]), j * 128 + cc * 32 + e) - gmax) * inv;
                    const uint32_t bH = (cc < 2) ? FA_P_H0 : FA_P_H1;
                    const uint32_t bL = (cc < 2) ? FA_P_L0 : FA_P_L1;
                    const int kb = (cc & 1) * 32;
                    #pragma unroll
                    for (int g = 0; g < 4; g++) {
                        uint32_t H[4], L[4];
                        #pragma unroll
                        for (int e2 = 0; e2 < 4; e2++) {
                            bf16 h0, l0, h1, l1;
                            split2(p[g * 8 + e2 * 2],     h0, l0);
                            split2(p[g * 8 + e2 * 2 + 1], h1, l1);
                            H[e2] = (uint32_t)__bfloat16_as_ushort(h0) | ((uint32_t)__bfloat16_as_ushort(h1) << 16);
                            L[e2] = (uint32_t)__bfloat16_as_ushort(l0) | ((uint32_t)__bfloat16_as_ushort(l1) << 16);
                        }
                        uint32_t off = (uint32_t)((rowl << 7) + ((kb + g * 8) << 1));
                        uint32_t sw = off ^ ((off >> 3) & 0x70);
                        STS128X(H[0], H[1], H[2], H[3], sb + bH + sw);
                        STS128X(L[0], L[1], L[2], L[3], sb + bL + sw);
                    }
                }
            }
            asm volatile("cp.async.wait_group 0;");
            __syncthreads();
            FENCE_PROXY_ASYNC();

            if (wid == 0) {
                if (elect_one_pred()) {
                    #pragma unroll
                    for (int t = 0; t < 2; t++) {
                        uint64_t dA  = MAKE_SMEM_DESC(sb + (t ? FA_P_H1 : FA_P_H0));
                        uint64_t dAl = MAKE_SMEM_DESC(sb + (t ? FA_P_L1 : FA_P_L0));
                        uint64_t dB  = MAKE_SMEM_DESC(sb + (t ? FA_VT_H1 : FA_VT_H0));
                        uint64_t dBl = MAKE_SMEM_DESC(sb + (t ? FA_VT_L1 : FA_VT_L0));
                        #pragma unroll
                        for (int s = 0; s < 4; s++) {
                            uint32_t en0 = (j == 0 && t == 0 && s == 0) ? 0u : 1u;
                            mma_f16_ss(tmem, dA + s*2, dB + s*2, ID_C, en0);
                            mma_f16_ss(tmem, dA + s*2, dBl + s*2, ID_C, 1u);
                            mma_f16_ss(tmem, dAl + s*2, dB + s*2, ID_C, 1u);
                        }
                    }
                    TCGEN05_COMMIT(sb + FA_MBAR);
                }
            }
            MBARRIER_WAIT_PARITY(sb + FA_MBAR, ph); ph ^= 1;
            TCGEN05_FENCE_AFTER();
        }
    };

    // ---------- branch 2 (QK) ----------
    do_branch(0);
    // stash ctx2 (cols 0..63) to SMEM over dead Q tile, layout [c][row]
    if (wid < 4) {
        int r = wid * 32 + lane;
        for (int cb = 0; cb < 2; cb++) {
            uint32_t d[32];
            TCGEN05_LD_32X32B_X32(d, tmem + cb * 32);
            TCGEN05_WAIT_LD();
            #pragma unroll
            for (int c = 0; c < 32; c++) stash[(cb * 32 + c) * 128 + r] = __uint_as_float(d[c]);
        }
    }
    TCGEN05_FENCE_BEFORE();
    __syncthreads();

    // reload key buffers with C keys
    tileload(FA_BK0_H, FA_BK0_L, keybase + 1536 + zh * 64, 256);
    tileload(FA_BK1_H, FA_BK1_L, keybase + 1536 + zh * 64 + 256LL * 3072, 256);
    asm volatile("cp.async.commit_group;");
    asm volatile("cp.async.wait_group 0;");
    FENCE_PROXY_ASYNC();
    __syncthreads();

    // ---------- branch 1 (cosine) ----------
    do_branch(1);

    // combine + write ctx pair
    if (wid < 4) {
        int r = wid * 32 + lane;
        long long ob = (long long)(zb * NS + m0 + r) * 768 + zh * 64;
        for (int cb = 0; cb < 2; cb++) {
            uint32_t d[32];
            TCGEN05_LD_32X32B_X32(d, tmem + cb * 32);
            TCGEN05_WAIT_LD();
            #pragma unroll
            for (int c = 0; c < 32; c += 2) {
                float v0 = __uint_as_float(d[c])     + stash[(cb * 32 + c) * 128 + r];
                float v1 = __uint_as_float(d[c + 1]) + stash[(cb * 32 + c + 1) * 128 + r];
                bf16 h0, l0, h1, l1;
                split2(v0, h0, l0);
                split2(v1, h1, l1);
                *(__nv_bfloat162*)(OH + ob + cb * 32 + c) = __nv_bfloat162(h0, h1);
                *(__nv_bfloat162*)(OL + ob + cb * 32 + c) = __nv_bfloat162(l0, l1);
            }
        }
    }
    TCGEN05_FENCE_BEFORE();
    __syncthreads();
    if (tid == 0) MBARRIER_INVAL(sb + FA_MBAR);
    if (wid == 4) TCGEN05_DEALLOC(tmem, 512);
#else
    // naive fallback (never selected on sm_103a hardware)
    if (tid < 128) {
        int m = tid;
        int grow = m0 + m;
        const float* cn = CNG + bh * 512;
        const long long rb = (long long)(zb * NS + grow) * 3072 + zh * 64;
        const long long kb = (long long)(zb * NS) * 3072 + zh * 64;
        float s1[512], s2[512];
        for (int r = 0; r < 512; r++) {
            float d1 = 0.f, d2 = 0.f;
            for (int k = 0; k < 64; k++) {
                float qv = __bfloat162float(PRH[rb + k]) + __bfloat162float(PRL[rb + k]);
                float cv = __bfloat162float(PRH[rb + 1536 + k]) + __bfloat162float(PRL[rb + 1536 + k]);
                long long kr = kb + (long long)r * 3072;
                float kv = __bfloat162float(PRH[kr + 768 + k]) + __bfloat162float(PRL[kr + 768 + k]);
                float cr = __bfloat162float(PRH[kr + 1536 + k]) + __bfloat162float(PRL[kr + 1536 + k]);
                d2 += qv * kv;
                d1 += cv * cr;
            }
            s2[r] = d2 * 0.125f;
            s1[r] = 1.0f - d1 * cn[grow] * cn[r] + ((r == grow) ? 1.0f : 0.0f);
        }
        float m1 = -1e30f, m2 = -1e30f;
        for (int r = 0; r < 512; r++) { m1 = fmaxf(m1, s1[r]); m2 = fmaxf(m2, s2[r]); }
        float t1 = 0.f, t2 = 0.f;
        for (int r = 0; r < 512; r++) {
            s1[r] = __expf(s1[r] - m1); t1 += s1[r];
            s2[r] = __expf(s2[r] - m2); t2 += s2[r];
        }
        for (int d = 0; d < 64; d++) {
            float acc = 0.f;
            for (int r = 0; r < 512; r++) {
                float p = 0.5f * s1[r] / t1 + 0.5f * s2[r] / t2;
                long long vr = kb + (long long)r * 3072 + 2304 + d;
                acc += p * (__bfloat162float(PRH[vr]) + __bfloat162float(PRL[vr]));
            }
            long long o = (long long)(zb * NS + grow) * 768 + zh * 64 + d;
            split2(acc, OH[o], OL[o]);
        }
    }
#endif
}

// ---------------- cnorm: 1/||c_r|| per (bh, r) ----------------
__global__ void cnorm_kernel(const bf16* __restrict__ ph, const bf16* __restrict__ pl,
                             float* __restrict__ cn)
{
    int w = (blockIdx.x << 3) + (threadIdx.x >> 5);
    int lane = threadIdx.x & 31;
    int bh = w >> 9, r = w & 511;
    int zb = bh / NH, zh = bh % NH;
    long long g = (long long)(zb * NS + r) * 3072 + 1536 + zh * 64 + lane * 2;
    float a = __bfloat162float(ph[g])     + __bfloat162float(pl[g]);
    float b = __bfloat162float(ph[g + 1]) + __bfloat162float(pl[g + 1]);
    float s = a * a + b * b;
    #pragma unroll
    for (int o = 16; o; o >>= 1) s += __shfl_xor_sync(0xffffffffu, s, o);
    if (lane == 0) cn[w] = rsqrtf(s);
}

// ---------------- fp32 -> bf16 hi/lo split ----------------
__global__ void conv_pair(const float4* __restrict__ src, bf16* __restrict__ h,
                          bf16* __restrict__ l, int n4)
{
    int i = blockIdx.x * 256 + threadIdx.x;
    if (i < n4) {
        float4 v = src[i];
        int b = i * 4;
        split2(v.x, h[b], l[b]);
        split2(v.y, h[b + 1], l[b + 1]);
        split2(v.z, h[b + 2], l[b + 2]);
        split2(v.w, h[b + 3], l[b + 3]);
    }
}

// ---------------- transpose + split ----------------
__global__ void transpose_split(const float* __restrict__ src, long long sS,
                                bf16* __restrict__ dh, bf16* __restrict__ dl, long long sD,
                                int R, int C, int lds, int ldd)
{
    __shared__ float t[32][33];
    const float* s = src + (long long)blockIdx.z * sS;
    bf16* oh = dh + (long long)blockIdx.z * sD;
    bf16* ol = dl + (long long)blockIdx.z * sD;
    int r0 = blockIdx.y * 32, c0 = blockIdx.x * 32;
    int tx = threadIdx.x, ty = threadIdx.y;
    #pragma unroll
    for (int i = 0; i < 4; i++) {
        int r = r0 + ty + i * 8;
        if (r < R && c0 + tx < C) t[ty + i * 8][tx] = s[(long long)r * lds + c0 + tx];
    }
    __syncthreads();
    #pragma unroll
    for (int i = 0; i < 4; i++) {
        int c = c0 + ty + i * 8, r = r0 + tx;
        if (c < C && r < R) {
            long long o = (long long)c * ldd + r;
            split2(t[tx][ty + i * 8], oh[o], ol[o]);
        }
    }
}

// ---------------- pair transpose (V -> Vt per head) ----------------
__global__ void transpose_pair(const bf16* __restrict__ sh, const bf16* __restrict__ sl,
                               long long sSb, long long sSh, int Hdiv,
                               bf16* __restrict__ dh, bf16* __restrict__ dl, long long sD,
                               int R, int C, int lds, int ldd)
{
    __shared__ uint32_t t[32][33];
    int zb = blockIdx.z / Hdiv, zh = blockIdx.z % Hdiv;
    long long so = zb * sSb + zh * sSh;
    bf16* oh = dh + (long long)blockIdx.z * sD;
    bf16* ol = dl + (long long)blockIdx.z * sD;
    int r0 = blockIdx.y * 32, c0 = blockIdx.x * 32;
    int tx = threadIdx.x, ty = threadIdx.y;
    #pragma unroll
    for (int i = 0; i < 4; i++) {
        int r = r0 + ty + i * 8;
        if (r < R && c0 + tx < C) {
            long long a = so + (long long)r * lds + c0 + tx;
            uint16_t hv = __bfloat16_as_ushort(sh[a]);
            uint16_t lv = __bfloat16_as_ushort(sl[a]);
            t[ty + i * 8][tx] = (uint32_t)hv | ((uint32_t)lv << 16);
        }
    }
    __syncthreads();
    #pragma unroll
    for (int i = 0; i < 4; i++) {
        int c = c0 + ty + i * 8, r = r0 + tx;
        if (c < C && r < R) {
            long long o = (long long)c * ldd + r;
            uint32_t v = t[tx][ty + i * 8];
            oh[o] = __ushort_as_bfloat16((uint16_t)(v & 0xffff));
            ol[o] = __ushort_as_bfloat16((uint16_t)(v >> 16));
        }
    }
}

// ---------------- block reduce (for LN) ----------------
__device__ __forceinline__ float block_reduce(float v, float* red)
{
    int lane = threadIdx.x & 31, w = threadIdx.x >> 5;
    #pragma unroll
    for (int o = 16; o; o >>= 1) v += __shfl_xor_sync(0xffffffffu, v, o);
    if (lane == 0) red[w] = v;
    __syncthreads();
    float r = red[0];
    #pragma unroll
    for (int i = 1; i < 8; i++) r += red[i];
    __syncthreads();
    return r;
}

// ---------------- residual add + LayerNorm ----------------
__global__ __launch_bounds__(256) void add_ln_kernel(
    const float* __restrict__ inp, const float* __restrict__ res,
    const float* __restrict__ g, const float* __restrict__ b,
    float* __restrict__ outf, bf16* __restrict__ outh, bf16* __restrict__ outl)
{
    long long row = blockIdx.x;
    const float* ip = inp + row * ND;
    const float* rp = res + row * ND;
    int t = threadIdx.x;

    __shared__ float buf[ND];
    __shared__ float red[8];

    float s = 0.f;
    for (int c = t; c < ND; c += 256) {
        float v = ip[c] + rp[c];
        buf[c] = v;
        s += v;
    }
    s = block_reduce(s, red);
    float mu = s * (1.0f / ND);
    float vs = 0.f;
    for (int c = t; c < ND; c += 256) {
        float d = buf[c] - mu;
        vs += d * d;
    }
    vs = block_reduce(vs, red);
    float inv = rsqrtf(vs * (1.0f / ND) + 1e-12f);
    for (int c = t; c < ND; c += 256) {
        float v = (buf[c] - mu) * inv * g[c] + b[c];
        long long o = row * ND + c;
        outf[o] = v;
        split2(v, outh[o], outl[o]);
    }
}

// ---------------- host ----------------
static float* symf(const void* s) { void* p = nullptr; cudaGetSymbolAddress(&p, s); return (float*)p; }
static bf16*  symb(const void* s) { void* p = nullptr; cudaGetSymbolAddress(&p, s); return (bf16*)p; }

#define SMEMSZ(TN, nst) ((nst) * ((128 + (TN)) * 256) + 64)

extern "C" void kernel_launch(void* const* d_in, const int* in_sizes, int n_in,
                              void* d_out, int out_size)
{
    const float* hs  = (const float*)d_in[0];
    const float* Wq  = (const float*)d_in[1];  const float* bq  = (const float*)d_in[2];
    const float* Wk  = (const float*)d_in[3];  const float* bk  = (const float*)d_in[4];
    const float* Wv  = (const float*)d_in[5];  const float* bv  = (const float*)d_in[6];
    const float* Wc  = (const float*)d_in[7];  const float* bc  = (const float*)d_in[8];
    const float* Wo  = (const float*)d_in[9];  const float* bo  = (const float*)d_in[10];
    const float* g1  = (const float*)d_in[11]; const float* b1  = (const float*)d_in[12];
    const float* Wi  = (const float*)d_in[13]; const float* bi  = (const float*)d_in[14];
    const float* Wo2 = (const float*)d_in[15]; const float* bo2 = (const float*)d_in[16];
    const float* g2  = (const float*)d_in[17]; const float* b2  = (const float*)d_in[18];

    const int SM256_2 = SMEMSZ(256, 2);

    cudaFuncSetAttribute(gemm_tc<1, 256>, cudaFuncAttributeMaxDynamicSharedMemorySize, SM256_2);
    cudaFuncSetAttribute(gemm_tc<2, 256>, cudaFuncAttributeMaxDynamicSharedMemorySize, SM256_2);
    cudaFuncSetAttribute(gemm_tc<4, 256>, cudaFuncAttributeMaxDynamicSharedMemorySize, SM256_2);
    cudaFuncSetAttribute(fused_attn,      cudaFuncAttributeMaxDynamicSharedMemorySize, FA_SMEM);

    float* XF   = symf(g_xf);
    float* TMP  = symf(g_tmp);
    float* ATTF = symf(g_attnf);
    float* CN   = symf(g_cninv);
    float* BCAT = symf(g_bcat);

    bf16 *XH = symb(g_xh), *XL = symb(g_xl);
    bf16 *PRJH = symb(g_prjh), *PRJL = symb(g_prjl);
    bf16 *CXH = symb(g_ctxh), *CXL = symb(g_ctxl);
    bf16 *ATH = symb(g_ath), *ATL = symb(g_atl);
    bf16 *HH = symb(g_hh), *HL = symb(g_hl);
    bf16 *VTH = symb(g_vth), *VTL = symb(g_vtl);

    bf16 *WCATH = symb(g_wcath), *WCATL = symb(g_wcatl);
    bf16 *WOH = symb(g_woh), *WOL = symb(g_wol);
    bf16 *WIH = symb(g_wih), *WIL = symb(g_wil);
    bf16 *WO2H = symb(g_wo2h), *WO2L = symb(g_wo2l);

    const long long SDP = (long long)NS * (4 * ND);
    const long long VTS = (long long)NDH * NS;

    const uint32_t ID256 = 0x8000490u | (32u << 17);

    dim3 tb(32, 8);
    transpose_split<<<dim3(24, 24, NL), tb>>>(Wq, WDD, WCATH + 0*WDD, WCATL + 0*WDD, CATW, 768, 768, 768, 768);
    transpose_split<<<dim3(24, 24, NL), tb>>>(Wk, WDD, WCATH + 1*WDD, WCATL + 1*WDD, CATW, 768, 768, 768, 768);
    transpose_split<<<dim3(24, 24, NL), tb>>>(Wc, WDD, WCATH + 2*WDD, WCATL + 2*WDD, CATW, 768, 768, 768, 768);
    transpose_split<<<dim3(24, 24, NL), tb>>>(Wv, WDD, WCATH + 3*WDD, WCATL + 3*WDD, CATW, 768, 768, 768, 768);
    transpose_split<<<dim3(24, 24, NL), tb>>>(Wo,  WDD, WOH,  WOL,  WDD, 768, 768, 768, 768);
    transpose_split<<<dim3(96, 24, NL), tb>>>(Wi,  WDF, WIH,  WIL,  WDF, 768, 3072, 3072, 768);
    transpose_split<<<dim3(24, 96, NL), tb>>>(Wo2, WDF, WO2H, WO2L, WDF, 3072, 768, 768, 3072);

    for (int i = 0; i < NL; i++) {
        cudaMemcpyAsync(BCAT + i*4*ND + 0*ND, bq + i*ND, ND*4, cudaMemcpyDeviceToDevice);
        cudaMemcpyAsync(BCAT + i*4*ND + 1*ND, bk + i*ND, ND*4, cudaMemcpyDeviceToDevice);
        cudaMemcpyAsync(BCAT + i*4*ND + 2*ND, bc + i*ND, ND*4, cudaMemcpyDeviceToDevice);
        cudaMemcpyAsync(BCAT + i*4*ND + 3*ND, bv + i*ND, ND*4, cudaMemcpyDeviceToDevice);
    }

    cudaMemcpyAsync(XF, hs, sizeof(float) * MROWS * ND, cudaMemcpyDeviceToDevice);
    conv_pair<<<(MROWS * ND / 4 + 255) / 256, 256>>>((const float4*)hs, XH, XL, MROWS * ND / 4);

    for (int i = 0; i < NL; i++) {
        const size_t oDD = (size_t)i * WDD, oDF = (size_t)i * WDF, oCAT = (size_t)i * CATW;

        // fused q|k|c|v projection
        gemm_tc<2, 256><<<dim3(12, 64, 1), 256, SM256_2>>>(
            XH, XL, 768, 0, 0, WCATH + oCAT, WCATL + oCAT, 768, 0, 0,
            nullptr, PRJH, PRJL, 3072, 0, 0, BCAT + i*4*ND, 3072, 768, 1, ID256);

        // V^T per head
        transpose_pair<<<dim3(2, 16, NBH), tb>>>(PRJH + 3*ND, PRJL + 3*ND, SDP, NDH, NH,
                                                 VTH, VTL, VTS, 512, 64, 4*ND, 512);

        // c-norms
        cnorm_kernel<<<(NBH * NS) / 8, 256>>>(PRJH, PRJL, CN);

        // fused scores + dual softmax + blend + ctx
        fused_attn<<<dim3(4, NBH), 256, FA_SMEM>>>(PRJH, PRJL, VTH, VTL, CN, CXH, CXL);

        // attn_out = LN(ctx @ Wo + bo + x)
        gemm_tc<1, 256><<<dim3(3, 64, 1), 256, SM256_2>>>(
            CXH, CXL, 768, 0, 0, WOH + oDD, WOL + oDD, 768, 0, 0,
            TMP, nullptr, nullptr, 768, 0, 0, bo + i * ND, 768, 768, 1, ID256);
        add_ln_kernel<<<MROWS, 256>>>(TMP, XF, g1 + i * ND, b1 + i * ND, ATTF, ATH, ATL);

        // h = gelu(attn @ Wi + bi)
        gemm_tc<4, 256><<<dim3(12, 64, 1), 256, SM256_2>>>(
            ATH, ATL, 768, 0, 0, WIH + oDF, WIL + oDF, 768, 0, 0,
            nullptr, HH, HL, 3072, 0, 0, bi + i * NF, 3072, 768, 1, ID256);

        // x = LN(h @ Wo2 + bo2 + attn)
        gemm_tc<1, 256><<<dim3(3, 64, 1), 256, SM256_2>>>(
            HH, HL, 3072, 0, 0, WO2H + oDF, WO2L + oDF, 3072, 0, 0,
            TMP, nullptr, nullptr, 768, 0, 0, bo2 + i * ND, 768, 3072, 1, ID256);
        add_ln_kernel<<<MROWS, 256>>>(TMP, ATTF, g2 + i * ND, b2 + i * ND, XF, XH, XL);
    }

    cudaMemcpyAsync(d_out, XF, sizeof(float) * MROWS * ND, cudaMemcpyDeviceToDevice);
}